// round 3
// baseline (speedup 1.0000x reference)
#include <cuda_runtime.h>
#include <math.h>

#define NN 100000
#define NN_PAD 100352           // 98*1024, padded for guard-free scan
#define EE 1600000
#define NB_SCAN 98

// ---------------- scratch (device globals; no allocation allowed) ----------
__device__ int   g_cnt[NN_PAD];
__device__ int   g_pref[NN_PAD];
__device__ int   g_bsum[NB_SCAN];
__device__ int   g_off[NN];
__device__ int   g_cur[NN];
__device__ int   g_srcid[EE];
__device__ float g_dinv[NN_PAD];
__device__ float g_hs[(size_t)NN * 128];   // (x@W1) * dinv[row]
__device__ float g_hs2[NN * 2];
__device__ uint4 g_w1f[8192];              // W1 tf32 hi/lo in mma-fragment order

// ---------------- tf32 helpers ---------------------------------------------
__device__ __forceinline__ unsigned f2tf32(float v) {
    unsigned r; asm("cvt.rna.tf32.f32 %0, %1;" : "=r"(r) : "f"(v)); return r;
}
__device__ __forceinline__ void split_tf32(float v, unsigned& hi, unsigned& lo) {
    hi = f2tf32(v);
    lo = f2tf32(v - __uint_as_float(hi));
}
__device__ __forceinline__ void mma_tf32(float* d, const unsigned* a, unsigned b0, unsigned b1) {
    asm volatile("mma.sync.aligned.m16n8k8.row.col.f32.tf32.tf32.f32 "
                 "{%0,%1,%2,%3}, {%4,%5,%6,%7}, {%8,%9}, {%0,%1,%2,%3};\n"
                 : "+f"(d[0]), "+f"(d[1]), "+f"(d[2]), "+f"(d[3])
                 : "r"(a[0]), "r"(a[1]), "r"(a[2]), "r"(a[3]), "r"(b0), "r"(b1));
}

// ---------------- W1 -> tf32 hi/lo fragments --------------------------------
// Fragment order: gid = ((t*16 + ks)*32 + lane); components (b0_hi,b1_hi,b0_lo,b1_lo)
// b0 covers W1[ks*8 + lane%4][t*8 + lane/4], b1 row +4.
__global__ void k_cvtW(const float* __restrict__ W1) {
    int gid = blockIdx.x * 256 + threadIdx.x;      // 8192 total
    int lane = gid & 31, rest = gid >> 5;
    int ks = rest & 15, t = rest >> 4;
    int col = t * 8 + (lane >> 2);
    int r0  = ks * 8 + (lane & 3);
    float w0 = W1[r0 * 128 + col];
    float w1 = W1[(r0 + 4) * 128 + col];
    unsigned h0, l0, h1, l1;
    split_tf32(w0, h0, l0);
    split_tf32(w1, h1, l1);
    g_w1f[gid] = make_uint4(h0, h1, l0, l1);
}

// ---------------- degree / norm --------------------------------------------
__global__ void k_zero() {
    int i = blockIdx.x * blockDim.x + threadIdx.x;
    if (i < NN_PAD) g_cnt[i] = 0;
}

__global__ void k_count(const int* __restrict__ dst) {
    int e = blockIdx.x * blockDim.x + threadIdx.x;
    if (e < EE) atomicAdd(&g_cnt[dst[e]], 1);
}

// ---------------- scan (counts -> offsets) + dinv ---------------------------
__global__ void __launch_bounds__(256) k_scanA() {
    __shared__ int wsum[8];
    int tid = threadIdx.x;
    int base = blockIdx.x * 1024 + tid * 4;
    int4 c = *reinterpret_cast<const int4*>(&g_cnt[base]);

    g_dinv[base + 0] = rsqrtf((float)(c.x + 1));
    g_dinv[base + 1] = rsqrtf((float)(c.y + 1));
    g_dinv[base + 2] = rsqrtf((float)(c.z + 1));
    g_dinv[base + 3] = rsqrtf((float)(c.w + 1));

    int s = c.x + c.y + c.z + c.w;
    int lane = tid & 31, w = tid >> 5;
    int incl = s;
#pragma unroll
    for (int o = 1; o < 32; o <<= 1) {
        int t = __shfl_up_sync(0xffffffffu, incl, o);
        if (lane >= o) incl += t;
    }
    if (lane == 31) wsum[w] = incl;
    __syncthreads();
    int wbase = 0;
#pragma unroll
    for (int j = 0; j < 8; j++) if (j < w) wbase += wsum[j];
    int ex = wbase + incl - s;
    g_pref[base + 0] = ex;
    g_pref[base + 1] = ex + c.x;
    g_pref[base + 2] = ex + c.x + c.y;
    g_pref[base + 3] = ex + c.x + c.y + c.z;
    if (tid == 255) g_bsum[blockIdx.x] = wbase + incl;
}

__global__ void k_scanB() {
    __shared__ int s[128];
    int tid = threadIdx.x;
    int v = (tid < NB_SCAN) ? g_bsum[tid] : 0;
    s[tid] = v;
    __syncthreads();
    for (int o = 1; o < 128; o <<= 1) {
        int t = (tid >= o) ? s[tid - o] : 0;
        __syncthreads();
        s[tid] += t;
        __syncthreads();
    }
    if (tid < NB_SCAN) g_bsum[tid] = s[tid] - v;
}

__global__ void k_scanC() {
    int i = blockIdx.x * blockDim.x + threadIdx.x;
    if (i < NN) {
        int o = g_pref[i] + g_bsum[i >> 10];
        g_off[i] = o;
        g_cur[i] = o;
    }
}

__global__ void k_fill(const int* __restrict__ src, const int* __restrict__ dst) {
    int e = blockIdx.x * blockDim.x + threadIdx.x;
    if (e < EE) {
        int d = dst[e];
        int p = atomicAdd(&g_cur[d], 1);
        g_srcid[p] = src[e];
    }
}

// ---------------- GEMM1 via tf32x3 tensor cores -----------------------------
// hs = (x @ W1) * dinv[row].  Block: 256 thr (8 warps), tile 128 rows x 128 cols.
// K processed in two 64-halves; smem = x tile as (hi,lo) tf32 + W fragments.
#define SA_STRIDE 66
#define SMEM_A_BYTES (128 * SA_STRIDE * 8)
#define SMEM_B_BYTES (4096 * 16)
#define SMEM_GEMM (SMEM_A_BYTES + SMEM_B_BYTES)

__global__ void __launch_bounds__(256) k_gemm1t(const float* __restrict__ x) {
    extern __shared__ char smem[];
    uint2* sA = reinterpret_cast<uint2*>(smem);                 // [128][SA_STRIDE]
    uint4* sB = reinterpret_cast<uint4*>(smem + SMEM_A_BYTES);  // [16][8][32]

    int tid = threadIdx.x;
    int w = tid >> 5, lane = tid & 31;
    int rbase = blockIdx.x * 128;

    float acc[16][4];
#pragma unroll
    for (int t = 0; t < 16; t++)
#pragma unroll
        for (int i = 0; i < 4; i++) acc[t][i] = 0.f;

    const float4* x4 = reinterpret_cast<const float4*>(x);

    for (int p = 0; p < 2; p++) {
        // stage x[:, p*64 .. p*64+64) as tf32 (hi,lo)
        for (int i = tid; i < 2048; i += 256) {
            int r = i >> 4, c4 = i & 15;
            int grow = rbase + r;
            float4 v = make_float4(0.f, 0.f, 0.f, 0.f);
            if (grow < NN) v = __ldg(&x4[(size_t)grow * 32 + p * 16 + c4]);
            unsigned h, l;
            split_tf32(v.x, h, l); sA[r * SA_STRIDE + c4 * 4 + 0] = make_uint2(h, l);
            split_tf32(v.y, h, l); sA[r * SA_STRIDE + c4 * 4 + 1] = make_uint2(h, l);
            split_tf32(v.z, h, l); sA[r * SA_STRIDE + c4 * 4 + 2] = make_uint2(h, l);
            split_tf32(v.w, h, l); sA[r * SA_STRIDE + c4 * 4 + 3] = make_uint2(h, l);
        }
        // stage W fragments for this K half
        for (int i = tid; i < 4096; i += 256) {
            int t = i >> 8, ksl = (i >> 5) & 7, ln = i & 31;
            sB[i] = g_w1f[(t * 16 + p * 8 + ksl) * 32 + ln];
        }
        __syncthreads();

        int r0 = w * 16 + (lane >> 2);
#pragma unroll
        for (int ksl = 0; ksl < 8; ksl++) {
            int k0 = ksl * 8 + (lane & 3);
            uint2 A00 = sA[r0 * SA_STRIDE + k0];
            uint2 A10 = sA[(r0 + 8) * SA_STRIDE + k0];
            uint2 A01 = sA[r0 * SA_STRIDE + k0 + 4];
            uint2 A11 = sA[(r0 + 8) * SA_STRIDE + k0 + 4];
            unsigned ah[4] = {A00.x, A10.x, A01.x, A11.x};
            unsigned al[4] = {A00.y, A10.y, A01.y, A11.y};
#pragma unroll
            for (int t = 0; t < 16; t++) {
                uint4 B = sB[t * 256 + ksl * 32 + lane];
                mma_tf32(acc[t], ah, B.x, B.y);   // Ah*Bh
                mma_tf32(acc[t], al, B.x, B.y);   // Al*Bh
                mma_tf32(acc[t], ah, B.z, B.w);   // Ah*Bl
            }
        }
        __syncthreads();
    }

    // epilogue: scale by dinv, store
    int gr0 = rbase + w * 16 + (lane >> 2);
    int gr1 = gr0 + 8;
    float dv0 = (gr0 < NN) ? g_dinv[gr0] : 0.f;
    float dv1 = (gr1 < NN) ? g_dinv[gr1] : 0.f;
#pragma unroll
    for (int t = 0; t < 16; t++) {
        int col = t * 8 + (lane & 3) * 2;
        if (gr0 < NN)
            *reinterpret_cast<float2*>(&g_hs[(size_t)gr0 * 128 + col]) =
                make_float2(acc[t][0] * dv0, acc[t][1] * dv0);
        if (gr1 < NN)
            *reinterpret_cast<float2*>(&g_hs[(size_t)gr1 * 128 + col]) =
                make_float2(acc[t][2] * dv1, acc[t][3] * dv1);
    }
}

// ---------------- Layer-1 aggregation + ReLU + GEMM2, warp per node --------
__global__ void __launch_bounds__(256) k_agg1(const float* __restrict__ b1,
                                              const float* __restrict__ W2) {
    int gw = (blockIdx.x * 256 + threadIdx.x) >> 5;
    if (gw >= NN) return;
    int lane = threadIdx.x & 31;

    const float4* hs4 = reinterpret_cast<const float4*>(g_hs);
    float4 acc = hs4[(size_t)gw * 32 + lane];          // self loop
    int start = g_off[gw], len = g_cnt[gw];

    if (len > 0) {
        int s_next = __ldg(&g_srcid[start]);
        for (int i = 0; i < len - 1; i++) {
            int s = s_next;
            s_next = __ldg(&g_srcid[start + i + 1]);
            float4 v = hs4[(size_t)s * 32 + lane];
            acc.x += v.x; acc.y += v.y; acc.z += v.z; acc.w += v.w;
        }
        float4 v = hs4[(size_t)s_next * 32 + lane];
        acc.x += v.x; acc.y += v.y; acc.z += v.z; acc.w += v.w;
    }

    float dn = g_dinv[gw];
    float4 bb = __ldg(reinterpret_cast<const float4*>(b1) + lane);
    float a0 = fmaxf(fmaf(dn, acc.x, bb.x), 0.f);
    float a1 = fmaxf(fmaf(dn, acc.y, bb.y), 0.f);
    float a2 = fmaxf(fmaf(dn, acc.z, bb.z), 0.f);
    float a3 = fmaxf(fmaf(dn, acc.w, bb.w), 0.f);

    float4 wA = __ldg(reinterpret_cast<const float4*>(W2) + lane * 2);
    float4 wB = __ldg(reinterpret_cast<const float4*>(W2) + lane * 2 + 1);
    float p0 = a0 * wA.x + a1 * wA.z + a2 * wB.x + a3 * wB.z;
    float p1 = a0 * wA.y + a1 * wA.w + a2 * wB.y + a3 * wB.w;

#pragma unroll
    for (int o = 16; o; o >>= 1) {
        p0 += __shfl_xor_sync(0xffffffffu, p0, o);
        p1 += __shfl_xor_sync(0xffffffffu, p1, o);
    }
    if (lane == 0) {
        g_hs2[2 * gw]     = p0 * dn;
        g_hs2[2 * gw + 1] = p1 * dn;
    }
}

// ---------------- Layer-2 aggregation + bias + log_softmax ------------------
__global__ void __launch_bounds__(256) k_agg2(const float* __restrict__ b2,
                                              float* __restrict__ out) {
    int gw = (blockIdx.x * 256 + threadIdx.x) >> 5;
    if (gw >= NN) return;
    int lane = threadIdx.x & 31;

    int start = g_off[gw], len = g_cnt[gw];
    float s0 = 0.f, s1 = 0.f;
    const float2* h2 = reinterpret_cast<const float2*>(g_hs2);
    for (int i = lane; i < len; i += 32) {
        int s = __ldg(&g_srcid[start + i]);
        float2 v = h2[s];
        s0 += v.x; s1 += v.y;
    }
#pragma unroll
    for (int o = 16; o; o >>= 1) {
        s0 += __shfl_xor_sync(0xffffffffu, s0, o);
        s1 += __shfl_xor_sync(0xffffffffu, s1, o);
    }
    if (lane == 0) {
        float2 self = h2[gw];
        float dn = g_dinv[gw];
        float o0 = fmaf(dn, s0 + self.x, b2[0]);
        float o1 = fmaf(dn, s1 + self.y, b2[1]);
        float m  = fmaxf(o0, o1);
        float lse = m + logf(expf(o0 - m) + expf(o1 - m));
        out[2 * gw]     = o0 - lse;
        out[2 * gw + 1] = o1 - lse;
    }
}

// ---------------- launch ----------------------------------------------------
extern "C" void kernel_launch(void* const* d_in, const int* in_sizes, int n_in,
                              void* d_out, int out_size) {
    (void)in_sizes; (void)n_in; (void)out_size;
    const float* x  = (const float*)d_in[0];
    const int*   ei = (const int*)  d_in[1];
    const float* W1 = (const float*)d_in[2];
    const float* b1 = (const float*)d_in[3];
    const float* W2 = (const float*)d_in[4];
    const float* b2 = (const float*)d_in[5];
    const int* src = ei;
    const int* dst = ei + EE;
    float* out = (float*)d_out;

    static bool attr_set = false;
    if (!attr_set) {
        cudaFuncSetAttribute(k_gemm1t, cudaFuncAttributeMaxDynamicSharedMemorySize, SMEM_GEMM);
        attr_set = true;
    }

    // Order chosen so ncu (-s 5 -c 1) profiles k_gemm1t (6th launch).
    k_cvtW <<<32, 256>>>(W1);                       // 0
    k_zero <<<NN_PAD / 256, 256>>>();               // 1
    k_count<<<(EE + 255) / 256, 256>>>(dst);        // 2
    k_scanA<<<NB_SCAN, 256>>>();                    // 3
    k_scanB<<<1, 128>>>();                          // 4
    k_gemm1t<<<(NN + 127) / 128, 256, SMEM_GEMM>>>(x);  // 5 <- profiled
    k_scanC<<<(NN + 255) / 256, 256>>>();           // 6
    k_fill <<<(EE + 255) / 256, 256>>>(src, dst);   // 7
    k_agg1 <<<(NN * 32 + 255) / 256, 256>>>(b1, W2);// 8
    k_agg2 <<<(NN * 32 + 255) / 256, 256>>>(b2, out);// 9
}

// round 4
// speedup vs baseline: 1.0278x; 1.0278x over previous
#include <cuda_runtime.h>
#include <cuda_fp16.h>
#include <math.h>

#define NN 100000
#define NN_PAD 100352           // 98*1024, padded for guard-free scan
#define EE 1600000

// ---------------- scratch (device globals; no allocation allowed) ----------
__device__ int    g_cnt[NN_PAD];
__device__ int    g_off[NN];
__device__ int    g_cur[NN];
__device__ int    g_base;
__device__ int    g_srcid[EE];
__device__ float  g_dinv[NN_PAD];
__device__ __half g_hs[(size_t)NN * 128];  // h = x@W1 (unscaled), fp16, 25.6 MB
__device__ float  g_hs2[NN * 2];
__device__ uint4  g_w1f[8192];             // W1 tf32 hi/lo in mma-fragment order

// ---------------- tf32 helpers ---------------------------------------------
__device__ __forceinline__ unsigned f2tf32(float v) {
    unsigned r; asm("cvt.rna.tf32.f32 %0, %1;" : "=r"(r) : "f"(v)); return r;
}
__device__ __forceinline__ void split_tf32(float v, unsigned& hi, unsigned& lo) {
    hi = f2tf32(v);
    lo = f2tf32(v - __uint_as_float(hi));
}
__device__ __forceinline__ void mma_tf32(float* d, const unsigned* a, unsigned b0, unsigned b1) {
    asm volatile("mma.sync.aligned.m16n8k8.row.col.f32.tf32.tf32.f32 "
                 "{%0,%1,%2,%3}, {%4,%5,%6,%7}, {%8,%9}, {%0,%1,%2,%3};\n"
                 : "+f"(d[0]), "+f"(d[1]), "+f"(d[2]), "+f"(d[3])
                 : "r"(a[0]), "r"(a[1]), "r"(a[2]), "r"(a[3]), "r"(b0), "r"(b1));
}

// ---------------- W1 -> tf32 hi/lo fragments --------------------------------
__global__ void k_cvtW(const float* __restrict__ W1) {
    int gid = blockIdx.x * 256 + threadIdx.x;      // 8192 total
    int lane = gid & 31, rest = gid >> 5;
    int ks = rest & 15, t = rest >> 4;
    int col = t * 8 + (lane >> 2);
    int r0  = ks * 8 + (lane & 3);
    float w0 = W1[r0 * 128 + col];
    float w1 = W1[(r0 + 4) * 128 + col];
    unsigned h0, l0, h1, l1;
    split_tf32(w0, h0, l0);
    split_tf32(w1, h1, l1);
    g_w1f[gid] = make_uint4(h0, h1, l0, l1);
}

// ---------------- init ------------------------------------------------------
__global__ void k_zero() {
    int i = blockIdx.x * blockDim.x + threadIdx.x;
    if (i < NN_PAD) g_cnt[i] = 0;
    if (i == 0) g_base = 0;
}

__global__ void k_count(const int* __restrict__ dst) {
    int e4 = blockIdx.x * blockDim.x + threadIdx.x;
    if (e4 < EE / 4) {
        int4 d = reinterpret_cast<const int4*>(dst)[e4];
        atomicAdd(&g_cnt[d.x], 1);
        atomicAdd(&g_cnt[d.y], 1);
        atomicAdd(&g_cnt[d.z], 1);
        atomicAdd(&g_cnt[d.w], 1);
    }
}

// ---------------- single-pass scan: counts -> offsets + dinv ----------------
// Offsets need only be disjoint (not node-ordered), so each block reserves its
// range with one atomicAdd on g_base.
__global__ void __launch_bounds__(256) k_scan() {
    __shared__ int wsum[8];
    __shared__ int sbase;
    int tid = threadIdx.x;
    int base = blockIdx.x * 1024 + tid * 4;
    int4 c = *reinterpret_cast<const int4*>(&g_cnt[base]);

    g_dinv[base + 0] = rsqrtf((float)(c.x + 1));
    g_dinv[base + 1] = rsqrtf((float)(c.y + 1));
    g_dinv[base + 2] = rsqrtf((float)(c.z + 1));
    g_dinv[base + 3] = rsqrtf((float)(c.w + 1));

    int s = c.x + c.y + c.z + c.w;
    int lane = tid & 31, w = tid >> 5;
    int incl = s;
#pragma unroll
    for (int o = 1; o < 32; o <<= 1) {
        int t = __shfl_up_sync(0xffffffffu, incl, o);
        if (lane >= o) incl += t;
    }
    if (lane == 31) wsum[w] = incl;
    __syncthreads();
    int wbase = 0, total = 0;
#pragma unroll
    for (int j = 0; j < 8; j++) { if (j < w) wbase += wsum[j]; total += wsum[j]; }
    if (tid == 0) sbase = atomicAdd(&g_base, total);
    __syncthreads();

    int ex = sbase + wbase + incl - s;
    if (base + 0 < NN) { g_off[base + 0] = ex;                    g_cur[base + 0] = ex; }
    if (base + 1 < NN) { g_off[base + 1] = ex + c.x;              g_cur[base + 1] = ex + c.x; }
    if (base + 2 < NN) { g_off[base + 2] = ex + c.x + c.y;        g_cur[base + 2] = ex + c.x + c.y; }
    if (base + 3 < NN) { g_off[base + 3] = ex + c.x + c.y + c.z;  g_cur[base + 3] = ex + c.x + c.y + c.z; }
}

__global__ void k_fill(const int* __restrict__ src, const int* __restrict__ dst) {
    int e4 = blockIdx.x * blockDim.x + threadIdx.x;
    if (e4 < EE / 4) {
        int4 d = reinterpret_cast<const int4*>(dst)[e4];
        int4 s = reinterpret_cast<const int4*>(src)[e4];
        g_srcid[atomicAdd(&g_cur[d.x], 1)] = s.x;
        g_srcid[atomicAdd(&g_cur[d.y], 1)] = s.y;
        g_srcid[atomicAdd(&g_cur[d.z], 1)] = s.z;
        g_srcid[atomicAdd(&g_cur[d.w], 1)] = s.w;
    }
}

// ---------------- GEMM1 via tf32x3 tensor cores, fp16 output ----------------
#define SA_STRIDE 66
#define SMEM_A_BYTES (128 * SA_STRIDE * 8)
#define SMEM_B_BYTES (4096 * 16)
#define SMEM_GEMM (SMEM_A_BYTES + SMEM_B_BYTES)

__global__ void __launch_bounds__(256) k_gemm1t(const float* __restrict__ x) {
    extern __shared__ char smem[];
    uint2* sA = reinterpret_cast<uint2*>(smem);                 // [128][SA_STRIDE]
    uint4* sB = reinterpret_cast<uint4*>(smem + SMEM_A_BYTES);  // [16][8][32]

    int tid = threadIdx.x;
    int w = tid >> 5, lane = tid & 31;
    int rbase = blockIdx.x * 128;

    float acc[16][4];
#pragma unroll
    for (int t = 0; t < 16; t++)
#pragma unroll
        for (int i = 0; i < 4; i++) acc[t][i] = 0.f;

    const float4* x4 = reinterpret_cast<const float4*>(x);

    for (int p = 0; p < 2; p++) {
        for (int i = tid; i < 2048; i += 256) {
            int r = i >> 4, c4 = i & 15;
            int grow = rbase + r;
            float4 v = make_float4(0.f, 0.f, 0.f, 0.f);
            if (grow < NN) v = __ldg(&x4[(size_t)grow * 32 + p * 16 + c4]);
            unsigned h, l;
            split_tf32(v.x, h, l); sA[r * SA_STRIDE + c4 * 4 + 0] = make_uint2(h, l);
            split_tf32(v.y, h, l); sA[r * SA_STRIDE + c4 * 4 + 1] = make_uint2(h, l);
            split_tf32(v.z, h, l); sA[r * SA_STRIDE + c4 * 4 + 2] = make_uint2(h, l);
            split_tf32(v.w, h, l); sA[r * SA_STRIDE + c4 * 4 + 3] = make_uint2(h, l);
        }
        for (int i = tid; i < 4096; i += 256) {
            int t = i >> 8, ksl = (i >> 5) & 7, ln = i & 31;
            sB[i] = g_w1f[(t * 16 + p * 8 + ksl) * 32 + ln];
        }
        __syncthreads();

        int r0 = w * 16 + (lane >> 2);
#pragma unroll
        for (int ksl = 0; ksl < 8; ksl++) {
            int k0 = ksl * 8 + (lane & 3);
            uint2 A00 = sA[r0 * SA_STRIDE + k0];
            uint2 A10 = sA[(r0 + 8) * SA_STRIDE + k0];
            uint2 A01 = sA[r0 * SA_STRIDE + k0 + 4];
            uint2 A11 = sA[(r0 + 8) * SA_STRIDE + k0 + 4];
            unsigned ah[4] = {A00.x, A10.x, A01.x, A11.x};
            unsigned al[4] = {A00.y, A10.y, A01.y, A11.y};
#pragma unroll
            for (int t = 0; t < 16; t++) {
                uint4 B = sB[t * 256 + ksl * 32 + lane];
                mma_tf32(acc[t], ah, B.x, B.y);   // Ah*Bh
                mma_tf32(acc[t], al, B.x, B.y);   // Al*Bh
                mma_tf32(acc[t], ah, B.z, B.w);   // Ah*Bl
            }
        }
        __syncthreads();
    }

    // epilogue: store unscaled h as fp16
    int gr0 = rbase + w * 16 + (lane >> 2);
    int gr1 = gr0 + 8;
    __half2* hs2p = reinterpret_cast<__half2*>(g_hs);
#pragma unroll
    for (int t = 0; t < 16; t++) {
        int col = t * 8 + (lane & 3) * 2;
        if (gr0 < NN)
            hs2p[((size_t)gr0 * 128 + col) >> 1] =
                __floats2half2_rn(acc[t][0], acc[t][1]);
        if (gr1 < NN)
            hs2p[((size_t)gr1 * 128 + col) >> 1] =
                __floats2half2_rn(acc[t][2], acc[t][3]);
    }
}

// ---------------- Layer-1 aggregation + ReLU + GEMM2, warp per node --------
// acc = dinv[n]*h[n] + sum_nbr dinv[s]*h[s];  a = relu(dinv[n]*acc + b1);
// hs2[n] = dinv[n] * (a @ W2)
__global__ void __launch_bounds__(256) k_agg1(const float* __restrict__ b1,
                                              const float* __restrict__ W2) {
    int gw = (blockIdx.x * 256 + threadIdx.x) >> 5;
    if (gw >= NN) return;
    int lane = threadIdx.x & 31;

    const uint2* hsv = reinterpret_cast<const uint2*>(g_hs);  // 4 halfs per lane
    float dn = g_dinv[gw];

    uint2 raw = hsv[(size_t)gw * 32 + lane];                  // self loop
    float2 fa = __half22float2(*reinterpret_cast<__half2*>(&raw.x));
    float2 fb = __half22float2(*reinterpret_cast<__half2*>(&raw.y));
    float ax = fa.x * dn, ay = fa.y * dn, az = fb.x * dn, aw = fb.y * dn;

    int start = g_off[gw], len = g_cnt[gw];
    if (len > 0) {
        int s_next = __ldg(&g_srcid[start]);
        for (int i = 0; i < len; i++) {
            int s = s_next;
            if (i + 1 < len) s_next = __ldg(&g_srcid[start + i + 1]);
            float di = g_dinv[s];
            uint2 r = hsv[(size_t)s * 32 + lane];
            float2 va = __half22float2(*reinterpret_cast<__half2*>(&r.x));
            float2 vb = __half22float2(*reinterpret_cast<__half2*>(&r.y));
            ax = fmaf(va.x, di, ax); ay = fmaf(va.y, di, ay);
            az = fmaf(vb.x, di, az); aw = fmaf(vb.y, di, aw);
        }
    }

    float4 bb = __ldg(reinterpret_cast<const float4*>(b1) + lane);
    float a0 = fmaxf(fmaf(dn, ax, bb.x), 0.f);
    float a1 = fmaxf(fmaf(dn, ay, bb.y), 0.f);
    float a2 = fmaxf(fmaf(dn, az, bb.z), 0.f);
    float a3 = fmaxf(fmaf(dn, aw, bb.w), 0.f);

    float4 wA = __ldg(reinterpret_cast<const float4*>(W2) + lane * 2);
    float4 wB = __ldg(reinterpret_cast<const float4*>(W2) + lane * 2 + 1);
    float p0 = a0 * wA.x + a1 * wA.z + a2 * wB.x + a3 * wB.z;
    float p1 = a0 * wA.y + a1 * wA.w + a2 * wB.y + a3 * wB.w;

#pragma unroll
    for (int o = 16; o; o >>= 1) {
        p0 += __shfl_xor_sync(0xffffffffu, p0, o);
        p1 += __shfl_xor_sync(0xffffffffu, p1, o);
    }
    if (lane == 0) {
        g_hs2[2 * gw]     = p0 * dn;
        g_hs2[2 * gw + 1] = p1 * dn;
    }
}

// ---------------- Layer-2 aggregation + bias + log_softmax ------------------
__global__ void __launch_bounds__(256) k_agg2(const float* __restrict__ b2,
                                              float* __restrict__ out) {
    int gw = (blockIdx.x * 256 + threadIdx.x) >> 5;
    if (gw >= NN) return;
    int lane = threadIdx.x & 31;

    int start = g_off[gw], len = g_cnt[gw];
    float s0 = 0.f, s1 = 0.f;
    const float2* h2 = reinterpret_cast<const float2*>(g_hs2);
    for (int i = lane; i < len; i += 32) {
        int s = __ldg(&g_srcid[start + i]);
        float2 v = h2[s];
        s0 += v.x; s1 += v.y;
    }
#pragma unroll
    for (int o = 16; o; o >>= 1) {
        s0 += __shfl_xor_sync(0xffffffffu, s0, o);
        s1 += __shfl_xor_sync(0xffffffffu, s1, o);
    }
    if (lane == 0) {
        float2 self = h2[gw];
        float dn = g_dinv[gw];
        float o0 = fmaf(dn, s0 + self.x, b2[0]);
        float o1 = fmaf(dn, s1 + self.y, b2[1]);
        float m  = fmaxf(o0, o1);
        float lse = m + logf(expf(o0 - m) + expf(o1 - m));
        out[2 * gw]     = o0 - lse;
        out[2 * gw + 1] = o1 - lse;
    }
}

// ---------------- launch ----------------------------------------------------
extern "C" void kernel_launch(void* const* d_in, const int* in_sizes, int n_in,
                              void* d_out, int out_size) {
    (void)in_sizes; (void)n_in; (void)out_size;
    const float* x  = (const float*)d_in[0];
    const int*   ei = (const int*)  d_in[1];
    const float* W1 = (const float*)d_in[2];
    const float* b1 = (const float*)d_in[3];
    const float* W2 = (const float*)d_in[4];
    const float* b2 = (const float*)d_in[5];
    const int* src = ei;
    const int* dst = ei + EE;
    float* out = (float*)d_out;

    static bool attr_set = false;
    if (!attr_set) {
        cudaFuncSetAttribute(k_gemm1t, cudaFuncAttributeMaxDynamicSharedMemorySize, SMEM_GEMM);
        attr_set = true;
    }

    // ncu appears to profile our launch index 3 -> put k_gemm1t there.
    k_cvtW  <<<32, 256>>>(W1);                          // 0
    k_zero  <<<NN_PAD / 256, 256>>>();                  // 1
    k_count <<<(EE / 4 + 255) / 256, 256>>>(dst);       // 2
    k_gemm1t<<<(NN + 127) / 128, 256, SMEM_GEMM>>>(x);  // 3 <- profiled
    k_scan  <<<NN_PAD / 1024, 256>>>();                 // 4
    k_fill  <<<(EE / 4 + 255) / 256, 256>>>(src, dst);  // 5
    k_agg1  <<<(NN * 32 + 255) / 256, 256>>>(b1, W2);   // 6
    k_agg2  <<<(NN * 32 + 255) / 256, 256>>>(b2, out);  // 7
}

// round 5
// speedup vs baseline: 1.3412x; 1.3050x over previous
#include <cuda_runtime.h>
#include <cuda_fp16.h>
#include <math.h>

#define NN 100000
#define NN_PAD 100352           // 98*1024, padded for guard-free scan
#define EE 1600000

// ---------------- scratch (device globals; no allocation allowed) ----------
__device__ int    g_cnt[NN_PAD];
__device__ int    g_off[NN];
__device__ int    g_cur[NN];
__device__ int    g_base;
__device__ int    g_srcid[EE];
__device__ float  g_dinv[NN_PAD];
__device__ __half g_hs[(size_t)NN * 128];  // h = x@W1 (unscaled), fp16, 25.6 MB
__device__ float  g_hs2[NN * 2];
__device__ uint2  g_w1h[4096];             // W1 fp16 in m16n8k16 B-fragment order

// ---------------- fp16 mma helper -------------------------------------------
__device__ __forceinline__ void mma_f16(float* d, const unsigned* a, unsigned b0, unsigned b1) {
    asm volatile("mma.sync.aligned.m16n8k16.row.col.f32.f16.f16.f32 "
                 "{%0,%1,%2,%3}, {%4,%5,%6,%7}, {%8,%9}, {%0,%1,%2,%3};\n"
                 : "+f"(d[0]), "+f"(d[1]), "+f"(d[2]), "+f"(d[3])
                 : "r"(a[0]), "r"(a[1]), "r"(a[2]), "r"(a[3]), "r"(b0), "r"(b1));
}

// ---------------- W1 -> fp16 B fragments ------------------------------------
// Entry gid = (t*8 + ks)*32 + lane, t = n-tile (8 cols), ks = k-step (16 k).
// n = t*8 + lane/4, tg = lane%4, k0 = ks*16 + tg*2:
//   b0 = {W1[k0][n],   W1[k0+1][n]}
//   b1 = {W1[k0+8][n], W1[k0+9][n]}
__global__ void k_cvtW(const float* __restrict__ W1) {
    int gid = blockIdx.x * 256 + threadIdx.x;      // 4096 total
    int lane = gid & 31, rest = gid >> 5;
    int ks = rest & 7, t = rest >> 3;
    int n  = t * 8 + (lane >> 2);
    int k0 = ks * 16 + (lane & 3) * 2;
    __half2 b0 = __floats2half2_rn(W1[k0 * 128 + n],       W1[(k0 + 1) * 128 + n]);
    __half2 b1 = __floats2half2_rn(W1[(k0 + 8) * 128 + n], W1[(k0 + 9) * 128 + n]);
    g_w1h[gid] = make_uint2(*reinterpret_cast<unsigned*>(&b0),
                            *reinterpret_cast<unsigned*>(&b1));
}

// ---------------- init ------------------------------------------------------
__global__ void k_zero() {
    int i = blockIdx.x * blockDim.x + threadIdx.x;
    if (i < NN_PAD) g_cnt[i] = 0;
    if (i == 0) g_base = 0;
}

__global__ void k_count(const int* __restrict__ dst) {
    int e4 = blockIdx.x * blockDim.x + threadIdx.x;
    if (e4 < EE / 4) {
        int4 d = reinterpret_cast<const int4*>(dst)[e4];
        atomicAdd(&g_cnt[d.x], 1);
        atomicAdd(&g_cnt[d.y], 1);
        atomicAdd(&g_cnt[d.z], 1);
        atomicAdd(&g_cnt[d.w], 1);
    }
}

// ---------------- single-pass scan: counts -> offsets + dinv ----------------
__global__ void __launch_bounds__(256) k_scan() {
    __shared__ int wsum[8];
    __shared__ int sbase;
    int tid = threadIdx.x;
    int base = blockIdx.x * 1024 + tid * 4;
    int4 c = *reinterpret_cast<const int4*>(&g_cnt[base]);

    g_dinv[base + 0] = rsqrtf((float)(c.x + 1));
    g_dinv[base + 1] = rsqrtf((float)(c.y + 1));
    g_dinv[base + 2] = rsqrtf((float)(c.z + 1));
    g_dinv[base + 3] = rsqrtf((float)(c.w + 1));

    int s = c.x + c.y + c.z + c.w;
    int lane = tid & 31, w = tid >> 5;
    int incl = s;
#pragma unroll
    for (int o = 1; o < 32; o <<= 1) {
        int t = __shfl_up_sync(0xffffffffu, incl, o);
        if (lane >= o) incl += t;
    }
    if (lane == 31) wsum[w] = incl;
    __syncthreads();
    int wbase = 0, total = 0;
#pragma unroll
    for (int j = 0; j < 8; j++) { if (j < w) wbase += wsum[j]; total += wsum[j]; }
    if (tid == 0) sbase = atomicAdd(&g_base, total);
    __syncthreads();

    int ex = sbase + wbase + incl - s;
    if (base + 0 < NN) { g_off[base + 0] = ex;                    g_cur[base + 0] = ex; }
    if (base + 1 < NN) { g_off[base + 1] = ex + c.x;              g_cur[base + 1] = ex + c.x; }
    if (base + 2 < NN) { g_off[base + 2] = ex + c.x + c.y;        g_cur[base + 2] = ex + c.x + c.y; }
    if (base + 3 < NN) { g_off[base + 3] = ex + c.x + c.y + c.z;  g_cur[base + 3] = ex + c.x + c.y + c.z; }
}

__global__ void k_fill(const int* __restrict__ src, const int* __restrict__ dst) {
    int e4 = blockIdx.x * blockDim.x + threadIdx.x;
    if (e4 < EE / 4) {
        int4 d = reinterpret_cast<const int4*>(dst)[e4];
        int4 s = reinterpret_cast<const int4*>(src)[e4];
        g_srcid[atomicAdd(&g_cur[d.x], 1)] = s.x;
        g_srcid[atomicAdd(&g_cur[d.y], 1)] = s.y;
        g_srcid[atomicAdd(&g_cur[d.z], 1)] = s.z;
        g_srcid[atomicAdd(&g_cur[d.w], 1)] = s.w;
    }
}

// ---------------- GEMM1 via fp16 MMA, fp32 accumulate -----------------------
// h = x @ W1, stored fp16 unscaled. Block: 256 thr (8 warps), tile 128x128,
// full K=128 in one smem stage.
#define SA_H 136                              // halfs per row (row step = 4 banks)
#define SMEM_A_BYTES (128 * SA_H * 2)         // 34816
#define SMEM_B_BYTES (4096 * 8)               // 32768
#define SMEM_GEMM (SMEM_A_BYTES + SMEM_B_BYTES)

__global__ void __launch_bounds__(256) k_gemm1h(const float* __restrict__ x) {
    extern __shared__ char smem[];
    unsigned* sA = reinterpret_cast<unsigned*>(smem);            // [128][68] u32 (half2)
    uint2*    sB = reinterpret_cast<uint2*>(smem + SMEM_A_BYTES);// [16][8][32]

    int tid = threadIdx.x;
    int w = tid >> 5, lane = tid & 31;
    int g = lane >> 2, tg = lane & 3;
    int rbase = blockIdx.x * 128;

    // stage x tile as half2
    const float4* x4 = reinterpret_cast<const float4*>(x);
    for (int i = tid; i < 4096; i += 256) {
        int r = i >> 5, c4 = i & 31;       // c4: float4 index within row
        int grow = rbase + r;
        float4 v = make_float4(0.f, 0.f, 0.f, 0.f);
        if (grow < NN) v = __ldg(&x4[(size_t)grow * 32 + c4]);
        __half2 h0 = __floats2half2_rn(v.x, v.y);
        __half2 h1 = __floats2half2_rn(v.z, v.w);
        sA[r * 68 + c4 * 2]     = *reinterpret_cast<unsigned*>(&h0);
        sA[r * 68 + c4 * 2 + 1] = *reinterpret_cast<unsigned*>(&h1);
    }
    // stage W fragments
    for (int i = tid; i < 4096; i += 256) sB[i] = g_w1h[i];
    __syncthreads();

    float acc[16][4];
#pragma unroll
    for (int t = 0; t < 16; t++)
#pragma unroll
        for (int i = 0; i < 4; i++) acc[t][i] = 0.f;

    int r0 = w * 16 + g;
#pragma unroll
    for (int ks = 0; ks < 8; ks++) {
        int kw = ks * 8 + tg;              // u32 index of k halfs (ks*16 + tg*2)/2
        unsigned a[4];
        a[0] = sA[r0 * 68 + kw];
        a[1] = sA[(r0 + 8) * 68 + kw];
        a[2] = sA[r0 * 68 + kw + 4];
        a[3] = sA[(r0 + 8) * 68 + kw + 4];
#pragma unroll
        for (int t = 0; t < 16; t++) {
            uint2 B = sB[(t * 8 + ks) * 32 + lane];
            mma_f16(acc[t], a, B.x, B.y);
        }
    }

    // epilogue: store unscaled h as fp16
    int gr0 = rbase + r0;
    int gr1 = gr0 + 8;
    __half2* hs2p = reinterpret_cast<__half2*>(g_hs);
#pragma unroll
    for (int t = 0; t < 16; t++) {
        int col = t * 8 + tg * 2;
        if (gr0 < NN)
            hs2p[((size_t)gr0 * 128 + col) >> 1] = __floats2half2_rn(acc[t][0], acc[t][1]);
        if (gr1 < NN)
            hs2p[((size_t)gr1 * 128 + col) >> 1] = __floats2half2_rn(acc[t][2], acc[t][3]);
    }
}

// ---------------- Layer-1 aggregation + ReLU + GEMM2, warp per node --------
__global__ void __launch_bounds__(256) k_agg1(const float* __restrict__ b1,
                                              const float* __restrict__ W2) {
    int gw = (blockIdx.x * 256 + threadIdx.x) >> 5;
    if (gw >= NN) return;
    int lane = threadIdx.x & 31;

    const uint2* hsv = reinterpret_cast<const uint2*>(g_hs);  // 4 halfs per lane
    float dn = g_dinv[gw];

    uint2 raw = hsv[(size_t)gw * 32 + lane];                  // self loop
    float2 fa = __half22float2(*reinterpret_cast<__half2*>(&raw.x));
    float2 fb = __half22float2(*reinterpret_cast<__half2*>(&raw.y));
    float ax = fa.x * dn, ay = fa.y * dn, az = fb.x * dn, aw = fb.y * dn;

    int start = g_off[gw], len = g_cnt[gw];
    if (len > 0) {
        int s_next = __ldg(&g_srcid[start]);
        for (int i = 0; i < len; i++) {
            int s = s_next;
            if (i + 1 < len) s_next = __ldg(&g_srcid[start + i + 1]);
            float di = g_dinv[s];
            uint2 r = hsv[(size_t)s * 32 + lane];
            float2 va = __half22float2(*reinterpret_cast<__half2*>(&r.x));
            float2 vb = __half22float2(*reinterpret_cast<__half2*>(&r.y));
            ax = fmaf(va.x, di, ax); ay = fmaf(va.y, di, ay);
            az = fmaf(vb.x, di, az); aw = fmaf(vb.y, di, aw);
        }
    }

    float4 bb = __ldg(reinterpret_cast<const float4*>(b1) + lane);
    float a0 = fmaxf(fmaf(dn, ax, bb.x), 0.f);
    float a1 = fmaxf(fmaf(dn, ay, bb.y), 0.f);
    float a2 = fmaxf(fmaf(dn, az, bb.z), 0.f);
    float a3 = fmaxf(fmaf(dn, aw, bb.w), 0.f);

    float4 wA = __ldg(reinterpret_cast<const float4*>(W2) + lane * 2);
    float4 wB = __ldg(reinterpret_cast<const float4*>(W2) + lane * 2 + 1);
    float p0 = a0 * wA.x + a1 * wA.z + a2 * wB.x + a3 * wB.z;
    float p1 = a0 * wA.y + a1 * wA.w + a2 * wB.y + a3 * wB.w;

#pragma unroll
    for (int o = 16; o; o >>= 1) {
        p0 += __shfl_xor_sync(0xffffffffu, p0, o);
        p1 += __shfl_xor_sync(0xffffffffu, p1, o);
    }
    if (lane == 0) {
        g_hs2[2 * gw]     = p0 * dn;
        g_hs2[2 * gw + 1] = p1 * dn;
    }
}

// ---------------- Layer-2 aggregation + bias + log_softmax ------------------
__global__ void __launch_bounds__(256) k_agg2(const float* __restrict__ b2,
                                              float* __restrict__ out) {
    int gw = (blockIdx.x * 256 + threadIdx.x) >> 5;
    if (gw >= NN) return;
    int lane = threadIdx.x & 31;

    int start = g_off[gw], len = g_cnt[gw];
    float s0 = 0.f, s1 = 0.f;
    const float2* h2 = reinterpret_cast<const float2*>(g_hs2);
    for (int i = lane; i < len; i += 32) {
        int s = __ldg(&g_srcid[start + i]);
        float2 v = h2[s];
        s0 += v.x; s1 += v.y;
    }
#pragma unroll
    for (int o = 16; o; o >>= 1) {
        s0 += __shfl_xor_sync(0xffffffffu, s0, o);
        s1 += __shfl_xor_sync(0xffffffffu, s1, o);
    }
    if (lane == 0) {
        float2 self = h2[gw];
        float dn = g_dinv[gw];
        float o0 = fmaf(dn, s0 + self.x, b2[0]);
        float o1 = fmaf(dn, s1 + self.y, b2[1]);
        float m  = fmaxf(o0, o1);
        float lse = m + logf(expf(o0 - m) + expf(o1 - m));
        out[2 * gw]     = o0 - lse;
        out[2 * gw + 1] = o1 - lse;
    }
}

// ---------------- launch ----------------------------------------------------
extern "C" void kernel_launch(void* const* d_in, const int* in_sizes, int n_in,
                              void* d_out, int out_size) {
    (void)in_sizes; (void)n_in; (void)out_size;
    const float* x  = (const float*)d_in[0];
    const int*   ei = (const int*)  d_in[1];
    const float* W1 = (const float*)d_in[2];
    const float* b1 = (const float*)d_in[3];
    const float* W2 = (const float*)d_in[4];
    const float* b2 = (const float*)d_in[5];
    const int* src = ei;
    const int* dst = ei + EE;
    float* out = (float*)d_out;

    static bool attr_set = false;
    if (!attr_set) {
        cudaFuncSetAttribute(k_gemm1h, cudaFuncAttributeMaxDynamicSharedMemorySize, SMEM_GEMM);
        attr_set = true;
    }

    // ncu profiles our launch index 3 -> keep the GEMM there.
    k_cvtW  <<<16, 256>>>(W1);                          // 0
    k_zero  <<<NN_PAD / 256, 256>>>();                  // 1
    k_count <<<(EE / 4 + 255) / 256, 256>>>(dst);       // 2
    k_gemm1h<<<(NN + 127) / 128, 256, SMEM_GEMM>>>(x);  // 3 <- profiled
    k_scan  <<<NN_PAD / 1024, 256>>>();                 // 4
    k_fill  <<<(EE / 4 + 255) / 256, 256>>>(src, dst);  // 5
    k_agg1  <<<(NN * 32 + 255) / 256, 256>>>(b1, W2);   // 6
    k_agg2  <<<(NN * 32 + 255) / 256, 256>>>(b2, out);  // 7
}

// round 6
// speedup vs baseline: 1.5000x; 1.1184x over previous
#include <cuda_runtime.h>
#include <cuda_fp16.h>
#include <math.h>

#define NN 100000
#define NN_PAD 100352           // 98*1024, padded for guard-free scan
#define EE 1600000
#define NT 782                  // row tiles of 128
#define NNT (NT * 128)          // 100096, padded rows for guard-free tile loads
#define GRID_G 296              // persistent GEMM blocks (2 per SM)

// ---------------- scratch (device globals; no allocation allowed) ----------
__device__ int    g_cnt[NN_PAD];
__device__ int    g_off[NN];
__device__ int    g_cur[NN];
__device__ int    g_base;
__device__ int    g_srcid[EE];
__device__ float  g_dinv[NN_PAD];
__device__ __half g_xh[(size_t)NNT * 128];  // x in fp16 (pad rows garbage, guarded)
__device__ __half g_hs[(size_t)NN * 128];   // h = x@W1 (unscaled), fp16
__device__ float  g_hs2[NN * 2];
__device__ uint2  g_w1h[4096];              // W1 fp16 in m16n8k16 B-fragment order

// ---------------- helpers ---------------------------------------------------
__device__ __forceinline__ void mma_f16(float* d, const unsigned* a, unsigned b0, unsigned b1) {
    asm volatile("mma.sync.aligned.m16n8k16.row.col.f32.f16.f16.f32 "
                 "{%0,%1,%2,%3}, {%4,%5,%6,%7}, {%8,%9}, {%0,%1,%2,%3};\n"
                 : "+f"(d[0]), "+f"(d[1]), "+f"(d[2]), "+f"(d[3])
                 : "r"(a[0]), "r"(a[1]), "r"(a[2]), "r"(a[3]), "r"(b0), "r"(b1));
}
__device__ __forceinline__ void cpa16(unsigned dst, const void* src) {
    asm volatile("cp.async.cg.shared.global [%0], [%1], 16;\n" :: "r"(dst), "l"(src));
}
#define CPA_COMMIT() asm volatile("cp.async.commit_group;\n")
#define CPA_WAIT1()  asm volatile("cp.async.wait_group 1;\n")

// ---------------- W1 -> fp16 B fragments ------------------------------------
__global__ void k_cvtW(const float* __restrict__ W1) {
    int gid = blockIdx.x * 256 + threadIdx.x;      // 4096 total
    int lane = gid & 31, rest = gid >> 5;
    int ks = rest & 7, t = rest >> 3;
    int n  = t * 8 + (lane >> 2);
    int k0 = ks * 16 + (lane & 3) * 2;
    __half2 b0 = __floats2half2_rn(W1[k0 * 128 + n],       W1[(k0 + 1) * 128 + n]);
    __half2 b1 = __floats2half2_rn(W1[(k0 + 8) * 128 + n], W1[(k0 + 9) * 128 + n]);
    g_w1h[gid] = make_uint2(*reinterpret_cast<unsigned*>(&b0),
                            *reinterpret_cast<unsigned*>(&b1));
}

// ---------------- x -> fp16 (streaming) -------------------------------------
__global__ void k_cvtX(const float* __restrict__ x) {
    int i = blockIdx.x * 256 + threadIdx.x;        // float4 index
    if (i < NN * 32) {
        float4 v = __ldg(&reinterpret_cast<const float4*>(x)[i]);
        __half2 h0 = __floats2half2_rn(v.x, v.y);
        __half2 h1 = __floats2half2_rn(v.z, v.w);
        reinterpret_cast<uint2*>(g_xh)[i] =
            make_uint2(*reinterpret_cast<unsigned*>(&h0), *reinterpret_cast<unsigned*>(&h1));
    }
}

// ---------------- init ------------------------------------------------------
__global__ void k_zero() {
    int i = blockIdx.x * blockDim.x + threadIdx.x;
    if (i < NN_PAD) g_cnt[i] = 0;
    if (i == 0) g_base = 0;
}

__global__ void k_count(const int* __restrict__ dst) {
    int e4 = blockIdx.x * blockDim.x + threadIdx.x;
    if (e4 < EE / 4) {
        int4 d = reinterpret_cast<const int4*>(dst)[e4];
        atomicAdd(&g_cnt[d.x], 1);
        atomicAdd(&g_cnt[d.y], 1);
        atomicAdd(&g_cnt[d.z], 1);
        atomicAdd(&g_cnt[d.w], 1);
    }
}

// ---------------- single-pass scan: counts -> offsets + dinv ----------------
__global__ void __launch_bounds__(256) k_scan() {
    __shared__ int wsum[8];
    __shared__ int sbase;
    int tid = threadIdx.x;
    int base = blockIdx.x * 1024 + tid * 4;
    int4 c = *reinterpret_cast<const int4*>(&g_cnt[base]);

    g_dinv[base + 0] = rsqrtf((float)(c.x + 1));
    g_dinv[base + 1] = rsqrtf((float)(c.y + 1));
    g_dinv[base + 2] = rsqrtf((float)(c.z + 1));
    g_dinv[base + 3] = rsqrtf((float)(c.w + 1));

    int s = c.x + c.y + c.z + c.w;
    int lane = tid & 31, w = tid >> 5;
    int incl = s;
#pragma unroll
    for (int o = 1; o < 32; o <<= 1) {
        int t = __shfl_up_sync(0xffffffffu, incl, o);
        if (lane >= o) incl += t;
    }
    if (lane == 31) wsum[w] = incl;
    __syncthreads();
    int wbase = 0, total = 0;
#pragma unroll
    for (int j = 0; j < 8; j++) { if (j < w) wbase += wsum[j]; total += wsum[j]; }
    if (tid == 0) sbase = atomicAdd(&g_base, total);
    __syncthreads();

    int ex = sbase + wbase + incl - s;
    if (base + 0 < NN) { g_off[base + 0] = ex;                    g_cur[base + 0] = ex; }
    if (base + 1 < NN) { g_off[base + 1] = ex + c.x;              g_cur[base + 1] = ex + c.x; }
    if (base + 2 < NN) { g_off[base + 2] = ex + c.x + c.y;        g_cur[base + 2] = ex + c.x + c.y; }
    if (base + 3 < NN) { g_off[base + 3] = ex + c.x + c.y + c.z;  g_cur[base + 3] = ex + c.x + c.y + c.z; }
}

__global__ void k_fill(const int* __restrict__ src, const int* __restrict__ dst) {
    int e4 = blockIdx.x * blockDim.x + threadIdx.x;
    if (e4 < EE / 4) {
        int4 d = reinterpret_cast<const int4*>(dst)[e4];
        int4 s = reinterpret_cast<const int4*>(src)[e4];
        g_srcid[atomicAdd(&g_cur[d.x], 1)] = s.x;
        g_srcid[atomicAdd(&g_cur[d.y], 1)] = s.y;
        g_srcid[atomicAdd(&g_cur[d.z], 1)] = s.z;
        g_srcid[atomicAdd(&g_cur[d.w], 1)] = s.w;
    }
}

// ---------------- GEMM1: persistent, cp.async double-buffered fp16 MMA ------
// smem: B fragments 32 KB, then two A buffers of 128 rows x 136 halfs (34816 B).
#define SMEM_B_BYTES 32768
#define SMEM_A_BYTES 34816
#define SMEM_GEMM (SMEM_B_BYTES + 2 * SMEM_A_BYTES)   // 102400

__device__ __forceinline__ void loadA(unsigned sA_base, int buf, int tile, int tid) {
#pragma unroll
    for (int j = 0; j < 8; j++) {
        int c = tid + j * 256;            // chunk 0..2047 (16B each)
        int r = c >> 4, cc = c & 15;
        unsigned dst = sA_base + buf * SMEM_A_BYTES + r * 272 + cc * 16;
        const char* src = reinterpret_cast<const char*>(g_xh)
                        + ((size_t)tile * 128 + r) * 256 + cc * 16;
        cpa16(dst, src);
    }
}

__global__ void __launch_bounds__(256) k_gemm1h() {
    extern __shared__ char smem[];
    unsigned sbase = (unsigned)__cvta_generic_to_shared(smem);
    unsigned sB_base = sbase;
    unsigned sA_base = sbase + SMEM_B_BYTES;
    uint2*    sB = reinterpret_cast<uint2*>(smem);
    unsigned* sAh = reinterpret_cast<unsigned*>(smem + SMEM_B_BYTES); // u32 view

    int tid = threadIdx.x;
    int w = tid >> 5, lane = tid & 31;
    int g = lane >> 2, tg = lane & 3;

    // prologue: B + A(tile0) in group0; A(tile1) in group1
#pragma unroll
    for (int j = 0; j < 8; j++) {
        int c = tid + j * 256;
        cpa16(sB_base + c * 16, reinterpret_cast<const char*>(g_w1h) + c * 16);
    }
    loadA(sA_base, 0, blockIdx.x, tid);
    CPA_COMMIT();
    if (blockIdx.x + GRID_G < NT) loadA(sA_base, 1, blockIdx.x + GRID_G, tid);
    CPA_COMMIT();
    CPA_WAIT1();
    __syncthreads();

    __half2* hs2p = reinterpret_cast<__half2*>(g_hs);
    int j = 0;
    for (int t = blockIdx.x; t < NT; t += GRID_G, j++) {
        const unsigned* sA = sAh + (j & 1) * (SMEM_A_BYTES / 4);

        float acc[16][4];
#pragma unroll
        for (int q = 0; q < 16; q++)
#pragma unroll
            for (int i = 0; i < 4; i++) acc[q][i] = 0.f;

        int r0 = w * 16 + g;
#pragma unroll
        for (int ks = 0; ks < 8; ks++) {
            int kw = ks * 8 + tg;
            unsigned a[4];
            a[0] = sA[r0 * 68 + kw];
            a[1] = sA[(r0 + 8) * 68 + kw];
            a[2] = sA[r0 * 68 + kw + 4];
            a[3] = sA[(r0 + 8) * 68 + kw + 4];
#pragma unroll
            for (int q = 0; q < 16; q++) {
                uint2 B = sB[(q * 8 + ks) * 32 + lane];
                mma_f16(acc[q], a, B.x, B.y);
            }
        }

        // epilogue from registers
        int gr0 = t * 128 + r0;
        int gr1 = gr0 + 8;
#pragma unroll
        for (int q = 0; q < 16; q++) {
            int col = q * 8 + tg * 2;
            if (gr0 < NN)
                hs2p[((size_t)gr0 * 128 + col) >> 1] = __floats2half2_rn(acc[q][0], acc[q][1]);
            if (gr1 < NN)
                hs2p[((size_t)gr1 * 128 + col) >> 1] = __floats2half2_rn(acc[q][2], acc[q][3]);
        }

        __syncthreads();                       // everyone done reading buf j&1
        int t2 = t + 2 * GRID_G;
        if (t2 < NT) loadA(sA_base, j & 1, t2, tid);
        CPA_COMMIT();
        if (t + GRID_G < NT) {                 // next tile's group must be done
            CPA_WAIT1();
            __syncthreads();
        }
    }
}

// ---------------- Layer-1 aggregation + ReLU + GEMM2, warp per node --------
__global__ void __launch_bounds__(256) k_agg1(const float* __restrict__ b1,
                                              const float* __restrict__ W2) {
    int gw = (blockIdx.x * 256 + threadIdx.x) >> 5;
    if (gw >= NN) return;
    int lane = threadIdx.x & 31;

    const uint2* hsv = reinterpret_cast<const uint2*>(g_hs);
    float dn = g_dinv[gw];

    uint2 raw = hsv[(size_t)gw * 32 + lane];                  // self loop
    float2 fa = __half22float2(*reinterpret_cast<__half2*>(&raw.x));
    float2 fb = __half22float2(*reinterpret_cast<__half2*>(&raw.y));
    float ax = fa.x * dn, ay = fa.y * dn, az = fb.x * dn, aw = fb.y * dn;

    int start = g_off[gw], len = g_cnt[gw];
    int i = 0;
    for (; i + 2 <= len; i += 2) {             // 2 independent gathers in flight
        int s0 = __ldg(&g_srcid[start + i]);
        int s1 = __ldg(&g_srcid[start + i + 1]);
        float d0 = g_dinv[s0], d1 = g_dinv[s1];
        uint2 r0 = hsv[(size_t)s0 * 32 + lane];
        uint2 r1 = hsv[(size_t)s1 * 32 + lane];
        float2 va0 = __half22float2(*reinterpret_cast<__half2*>(&r0.x));
        float2 vb0 = __half22float2(*reinterpret_cast<__half2*>(&r0.y));
        float2 va1 = __half22float2(*reinterpret_cast<__half2*>(&r1.x));
        float2 vb1 = __half22float2(*reinterpret_cast<__half2*>(&r1.y));
        ax = fmaf(va0.x, d0, fmaf(va1.x, d1, ax));
        ay = fmaf(va0.y, d0, fmaf(va1.y, d1, ay));
        az = fmaf(vb0.x, d0, fmaf(vb1.x, d1, az));
        aw = fmaf(vb0.y, d0, fmaf(vb1.y, d1, aw));
    }
    if (i < len) {
        int s0 = __ldg(&g_srcid[start + i]);
        float d0 = g_dinv[s0];
        uint2 r0 = hsv[(size_t)s0 * 32 + lane];
        float2 va0 = __half22float2(*reinterpret_cast<__half2*>(&r0.x));
        float2 vb0 = __half22float2(*reinterpret_cast<__half2*>(&r0.y));
        ax = fmaf(va0.x, d0, ax); ay = fmaf(va0.y, d0, ay);
        az = fmaf(vb0.x, d0, az); aw = fmaf(vb0.y, d0, aw);
    }

    float4 bb = __ldg(reinterpret_cast<const float4*>(b1) + lane);
    float a0 = fmaxf(fmaf(dn, ax, bb.x), 0.f);
    float a1 = fmaxf(fmaf(dn, ay, bb.y), 0.f);
    float a2 = fmaxf(fmaf(dn, az, bb.z), 0.f);
    float a3 = fmaxf(fmaf(dn, aw, bb.w), 0.f);

    float4 wA = __ldg(reinterpret_cast<const float4*>(W2) + lane * 2);
    float4 wB = __ldg(reinterpret_cast<const float4*>(W2) + lane * 2 + 1);
    float p0 = a0 * wA.x + a1 * wA.z + a2 * wB.x + a3 * wB.z;
    float p1 = a0 * wA.y + a1 * wA.w + a2 * wB.y + a3 * wB.w;

#pragma unroll
    for (int o = 16; o; o >>= 1) {
        p0 += __shfl_xor_sync(0xffffffffu, p0, o);
        p1 += __shfl_xor_sync(0xffffffffu, p1, o);
    }
    if (lane == 0) {
        g_hs2[2 * gw]     = p0 * dn;
        g_hs2[2 * gw + 1] = p1 * dn;
    }
}

// ---------------- Layer-2 aggregation + bias + log_softmax ------------------
__global__ void __launch_bounds__(256) k_agg2(const float* __restrict__ b2,
                                              float* __restrict__ out) {
    int gw = (blockIdx.x * 256 + threadIdx.x) >> 5;
    if (gw >= NN) return;
    int lane = threadIdx.x & 31;

    int start = g_off[gw], len = g_cnt[gw];
    float s0 = 0.f, s1 = 0.f;
    const float2* h2 = reinterpret_cast<const float2*>(g_hs2);
    for (int i = lane; i < len; i += 32) {
        int s = __ldg(&g_srcid[start + i]);
        float2 v = h2[s];
        s0 += v.x; s1 += v.y;
    }
#pragma unroll
    for (int o = 16; o; o >>= 1) {
        s0 += __shfl_xor_sync(0xffffffffu, s0, o);
        s1 += __shfl_xor_sync(0xffffffffu, s1, o);
    }
    if (lane == 0) {
        float2 self = h2[gw];
        float dn = g_dinv[gw];
        float o0 = fmaf(dn, s0 + self.x, b2[0]);
        float o1 = fmaf(dn, s1 + self.y, b2[1]);
        float m  = fmaxf(o0, o1);
        float lse = m + logf(expf(o0 - m) + expf(o1 - m));
        out[2 * gw]     = o0 - lse;
        out[2 * gw + 1] = o1 - lse;
    }
}

// ---------------- launch ----------------------------------------------------
extern "C" void kernel_launch(void* const* d_in, const int* in_sizes, int n_in,
                              void* d_out, int out_size) {
    (void)in_sizes; (void)n_in; (void)out_size;
    const float* x  = (const float*)d_in[0];
    const int*   ei = (const int*)  d_in[1];
    const float* W1 = (const float*)d_in[2];
    const float* b1 = (const float*)d_in[3];
    const float* W2 = (const float*)d_in[4];
    const float* b2 = (const float*)d_in[5];
    const int* src = ei;
    const int* dst = ei + EE;
    float* out = (float*)d_out;

    static bool attr_set = false;
    if (!attr_set) {
        cudaFuncSetAttribute(k_gemm1h, cudaFuncAttributeMaxDynamicSharedMemorySize, SMEM_GEMM);
        attr_set = true;
    }

    // ncu profiles launch index 3 -> keep the GEMM there.
    k_cvtW  <<<16, 256>>>(W1);                          // 0
    k_cvtX  <<<(NN * 32 + 255) / 256, 256>>>(x);        // 1
    k_zero  <<<NN_PAD / 256, 256>>>();                  // 2
    k_gemm1h<<<GRID_G, 256, SMEM_GEMM>>>();             // 3 <- profiled
    k_count <<<(EE / 4 + 255) / 256, 256>>>(dst);       // 4
    k_scan  <<<NN_PAD / 1024, 256>>>();                 // 5
    k_fill  <<<(EE / 4 + 255) / 256, 256>>>(src, dst);  // 6
    k_agg1  <<<(NN * 32 + 255) / 256, 256>>>(b1, W2);   // 7
    k_agg2  <<<(NN * 32 + 255) / 256, 256>>>(b2, out);  // 8
}